// round 4
// baseline (speedup 1.0000x reference)
#include <cuda_runtime.h>
#include <cuda_bf16.h>
#include <cuda_fp16.h>

// Problem constants
#define BB 2
#define LL 1024
#define CA 512
#define CS 384
#define CZ 64
#define HH 16
#define DD 32
#define MM (BB*LL)          // 2048 rows
#define SCALE 0.17677669529663687f  // 1/sqrt(32)

typedef unsigned long long U64;
__device__ __forceinline__ U64 pk2(float lo, float hi){ U64 r; asm("mov.b64 %0, {%1,%2};":"=l"(r):"f"(lo),"f"(hi)); return r; }
__device__ __forceinline__ void fma2(U64 &d, U64 a, U64 b){ asm("fma.rn.f32x2 %0, %1, %2, %3;":"=l"(d):"l"(a),"l"(b),"l"(d)); }
__device__ __forceinline__ float2 up2(U64 v){ float2 r; asm("mov.b64 {%0,%1}, %2;":"=f"(r.x),"=f"(r.y):"l"(v)); return r; }

// -------------------- device scratch --------------------
__device__ __align__(16) float g_s_ln[MM*CS];
__device__ __align__(16) float g_a_ln[MM*CA];
__device__ __align__(16) float g_anorm[MM*CA];
__device__ __align__(16) float g_glast[MM*CA];
__device__ __align__(16) float g_q[MM*CA];   // [b][h][l][d]
__device__ __align__(16) float g_k[MM*CA];
__device__ __align__(16) float g_v[MM*CA];
__device__ __align__(16) float g_g[MM*CA];   // pre-sigmoid gate
__device__ __align__(16) float g_ao[MM*CA];  // attention out [b][l][h*32+d]
__device__ __align__(16) __half g_biash[(size_t)BB*HH*LL*LL]; // 67MB fp16 bias

__device__ __forceinline__ float sigm(float x){ return 1.f/(1.f+__expf(-x)); }

// -------------------- kernel 1: row layernorms --------------------
__global__ __launch_bounds__(256) void ln_kernel(
    const float* __restrict__ a, const float* __restrict__ s,
    const float* __restrict__ s_scale)
{
    int row = blockIdx.x;
    int tid = threadIdx.x;
    __shared__ float rs[16];
    const float* ar = a + (size_t)row*CA;
    float x0 = ar[tid], x1 = ar[tid+256];
    float sum = x0+x1, ss = x0*x0 + x1*x1;
    #pragma unroll
    for(int o=16;o;o>>=1){ sum += __shfl_xor_sync(0xffffffffu,sum,o); ss += __shfl_xor_sync(0xffffffffu,ss,o); }
    if((tid&31)==0){ rs[tid>>5]=sum; rs[8+(tid>>5)]=ss; }
    __syncthreads();
    if(tid==0){ float S=0,Q=0; for(int i=0;i<8;i++){S+=rs[i];Q+=rs[8+i];} rs[0]=S; rs[8]=Q; }
    __syncthreads();
    float mean = rs[0]*(1.f/CA);
    float var  = rs[8]*(1.f/CA) - mean*mean;
    float rstd = rsqrtf(var + 1e-5f);
    g_a_ln[(size_t)row*CA + tid]      = (x0-mean)*rstd;
    g_a_ln[(size_t)row*CA + tid+256]  = (x1-mean)*rstd;
    __syncthreads();
    const float* sr = s + (size_t)row*CS;
    float y0 = sr[tid];
    float y1 = (tid < CS-256) ? sr[tid+256] : 0.f;
    sum = y0+y1; ss = y0*y0 + y1*y1;
    #pragma unroll
    for(int o=16;o;o>>=1){ sum += __shfl_xor_sync(0xffffffffu,sum,o); ss += __shfl_xor_sync(0xffffffffu,ss,o); }
    if((tid&31)==0){ rs[tid>>5]=sum; rs[8+(tid>>5)]=ss; }
    __syncthreads();
    if(tid==0){ float S=0,Q=0; for(int i=0;i<8;i++){S+=rs[i];Q+=rs[8+i];} rs[0]=S; rs[8]=Q; }
    __syncthreads();
    mean = rs[0]*(1.f/CS);
    var  = rs[8]*(1.f/CS) - mean*mean;
    rstd = rsqrtf(var + 1e-5f);
    g_s_ln[(size_t)row*CS + tid] = (y0-mean)*rstd*s_scale[tid];
    if(tid < CS-256)
        g_s_ln[(size_t)row*CS + tid+256] = (y1-mean)*rstd*s_scale[tid+256];
}

// -------------------- kernel 2: a_norm + glast (triple GEMM, f32x2) --------------------
__global__ __launch_bounds__(256) void anorm_kernel(
    const float* __restrict__ s_raw,
    const float* __restrict__ ada_w_s, const float* __restrict__ ada_b_s,
    const float* __restrict__ ada_w_nb,
    const float* __restrict__ w_last, const float* __restrict__ b_last)
{
    const int K = CS;
    __shared__ __align__(16) float As1[16][72];
    __shared__ __align__(16) float As2[16][72];
    __shared__ __align__(16) float Bs1[16][72];
    __shared__ __align__(16) float Bs2[16][72];
    __shared__ __align__(16) float Bs3[16][72];
    int tid = threadIdx.x;
    int tx = tid & 15, ty = tid >> 4;
    int m0 = blockIdx.y*64, n0 = blockIdx.x*64;
    U64 c1[4][2]={}, c2[4][2]={}, c3[4][2]={};
    for(int k0=0;k0<K;k0+=16){
        #pragma unroll
        for(int p=0;p<4;p++){
            int e = p*256 + tid;
            int mm = e>>4, kk = e&15;
            As1[kk][mm] = g_s_ln[(size_t)(m0+mm)*K + k0+kk];
            As2[kk][mm] = s_raw[(size_t)(m0+mm)*K + k0+kk];
            Bs1[kk][mm] = ada_w_s [(size_t)(n0+mm)*K + k0+kk];
            Bs2[kk][mm] = ada_w_nb[(size_t)(n0+mm)*K + k0+kk];
            Bs3[kk][mm] = w_last  [(size_t)(n0+mm)*K + k0+kk];
        }
        __syncthreads();
        #pragma unroll
        for(int kk=0;kk<16;kk++){
            float4 a1 = *(const float4*)&As1[kk][ty*4];
            float4 a2 = *(const float4*)&As2[kk][ty*4];
            ulonglong2 b1 = *(const ulonglong2*)&Bs1[kk][tx*4];
            ulonglong2 b2 = *(const ulonglong2*)&Bs2[kk][tx*4];
            ulonglong2 b3 = *(const ulonglong2*)&Bs3[kk][tx*4];
            U64 a1d[4], a2d[4];
            a1d[0]=pk2(a1.x,a1.x); a1d[1]=pk2(a1.y,a1.y); a1d[2]=pk2(a1.z,a1.z); a1d[3]=pk2(a1.w,a1.w);
            a2d[0]=pk2(a2.x,a2.x); a2d[1]=pk2(a2.y,a2.y); a2d[2]=pk2(a2.z,a2.z); a2d[3]=pk2(a2.w,a2.w);
            #pragma unroll
            for(int i=0;i<4;i++){
                fma2(c1[i][0],a1d[i],b1.x); fma2(c1[i][1],a1d[i],b1.y);
                fma2(c2[i][0],a1d[i],b2.x); fma2(c2[i][1],a1d[i],b2.y);
                fma2(c3[i][0],a2d[i],b3.x); fma2(c3[i][1],a2d[i],b3.y);
            }
        }
        __syncthreads();
    }
    #pragma unroll
    for(int i=0;i<4;i++){
        int m = m0 + ty*4 + i;
        #pragma unroll
        for(int jp=0;jp<2;jp++){
            float2 v1 = up2(c1[i][jp]), v2 = up2(c2[i][jp]), v3 = up2(c3[i][jp]);
            int n = n0 + tx*4 + jp*2;
            float sgA = sigm(v1.x + ada_b_s[n]);
            float sgB = sigm(v1.y + ada_b_s[n+1]);
            g_anorm[(size_t)m*CA + n]   = sgA * g_a_ln[(size_t)m*CA + n]   + v2.x;
            g_anorm[(size_t)m*CA + n+1] = sgB * g_a_ln[(size_t)m*CA + n+1] + v2.y;
            g_glast[(size_t)m*CA + n]   = sigm(v3.x + b_last[n]);
            g_glast[(size_t)m*CA + n+1] = sigm(v3.y + b_last[n+1]);
        }
    }
}

// -------------------- kernel 3: QKVG projections (f32x2) --------------------
__global__ __launch_bounds__(256) void qkvg_kernel(
    const float* __restrict__ wq, const float* __restrict__ bq,
    const float* __restrict__ wk, const float* __restrict__ bk,
    const float* __restrict__ wv, const float* __restrict__ bv,
    const float* __restrict__ wg, const float* __restrict__ bg)
{
    const int K = CA;
    __shared__ __align__(16) float As[16][136];
    __shared__ __align__(16) float Bs[16][136];
    int tid = threadIdx.x;
    int tx = tid & 15, ty = tid >> 4;
    int m0 = blockIdx.y*128;
    int n0 = blockIdx.x*128;
    int which = n0 >> 9;
    int nn0 = n0 & 511;
    const float* W  = (which==0)?wq : (which==1)?wk : (which==2)?wv : wg;
    const float* Bv = (which==0)?bq : (which==1)?bk : (which==2)?bv : bg;
    U64 c[8][4]={};
    for(int k0=0;k0<K;k0+=16){
        #pragma unroll
        for(int p=0;p<8;p++){
            int e = p*256 + tid;
            int mm = e>>4, kk = e&15;
            As[kk][mm] = g_anorm[(size_t)(m0+mm)*K + k0+kk];
            Bs[kk][mm] = W[(size_t)(nn0+mm)*K + k0+kk];
        }
        __syncthreads();
        #pragma unroll
        for(int kk=0;kk<16;kk++){
            float4 t0 = *(const float4*)&As[kk][ty*8];
            float4 t1 = *(const float4*)&As[kk][ty*8+4];
            ulonglong2 b0 = *(const ulonglong2*)&Bs[kk][tx*8];
            ulonglong2 b1 = *(const ulonglong2*)&Bs[kk][tx*8+4];
            U64 ad[8];
            ad[0]=pk2(t0.x,t0.x); ad[1]=pk2(t0.y,t0.y); ad[2]=pk2(t0.z,t0.z); ad[3]=pk2(t0.w,t0.w);
            ad[4]=pk2(t1.x,t1.x); ad[5]=pk2(t1.y,t1.y); ad[6]=pk2(t1.z,t1.z); ad[7]=pk2(t1.w,t1.w);
            #pragma unroll
            for(int i=0;i<8;i++){
                fma2(c[i][0],ad[i],b0.x); fma2(c[i][1],ad[i],b0.y);
                fma2(c[i][2],ad[i],b1.x); fma2(c[i][3],ad[i],b1.y);
            }
        }
        __syncthreads();
    }
    float* dst = (which==0)?g_q : (which==1)?g_k : g_v;
    #pragma unroll
    for(int i=0;i<8;i++){
        int m = m0 + ty*8 + i;
        #pragma unroll
        for(int jp=0;jp<4;jp++){
            float2 v = up2(c[i][jp]);
            #pragma unroll
            for(int l=0;l<2;l++){
                int nn = nn0 + tx*8 + jp*2 + l;
                float val = (l?v.y:v.x) + Bv[nn];
                if(which < 3){
                    int hh = nn>>5, dd2 = nn&31;
                    int bb = m>>10, ll = m&1023;
                    dst[(((size_t)(bb*HH+hh))*LL + ll)*DD + dd2] = val;
                } else {
                    g_g[(size_t)m*CA + nn] = val;
                }
            }
        }
    }
}

// -------------------- kernel 4: pair bias (2 rows x 8 heads/thread, packed weights) ----
// thread handles k-pair (t0, t0+1); accumulators packed over the row pair.
__global__ __launch_bounds__(256) void bias_kernel(
    const float* __restrict__ z, const float* __restrict__ z_scale,
    const float* __restrict__ wz)
{
    __shared__ __align__(16) U64 wzs2[HH][CZ];   // (w,w) packed, 8KB
    __shared__ float wsum[HH];
    int tid = threadIdx.x;
    for(int e=tid;e<HH*CZ;e+=256){
        float w = wz[e]*z_scale[e&63];
        wzs2[e>>6][e&63] = pk2(w,w);
    }
    __syncthreads();
    if(tid < HH){ float S=0.f; for(int c=0;c<CZ;c++){ float2 t=up2(wzs2[tid][c]); S+=t.x; } wsum[tid]=S; }
    __syncthreads();

    int lane  = tid & 127;
    int hbase = (tid >> 7) * 8;      // warps 0-3: heads 0-7, warps 4-7: heads 8-15
    size_t pairIdx = (size_t)blockIdx.x*128 + lane;
    size_t t0 = pairIdx*2;
    const float4* zp0 = (const float4*)(z + t0*CZ);
    const float4* zp1 = zp0 + 16;    // next row (contiguous)

    U64 acc[8];
    #pragma unroll
    for(int h2=0;h2<8;h2++) acc[h2]=0ull;
    U64 sum=0ull, ssq=0ull;
    const U64 one2 = pk2(1.f,1.f);

    #pragma unroll 4
    for(int cs=0;cs<16;cs++){
        float4 a = zp0[cs];
        float4 b = zp1[cs];
        U64 p0=pk2(a.x,b.x), p1=pk2(a.y,b.y), p2=pk2(a.z,b.z), p3=pk2(a.w,b.w);
        fma2(sum,p0,one2); fma2(sum,p1,one2); fma2(sum,p2,one2); fma2(sum,p3,one2);
        fma2(ssq,p0,p0);   fma2(ssq,p1,p1);   fma2(ssq,p2,p2);   fma2(ssq,p3,p3);
        #pragma unroll
        for(int h2=0;h2<8;h2++){
            const ulonglong2* wp = (const ulonglong2*)&wzs2[hbase+h2][cs*4];
            ulonglong2 wlo = wp[0];
            ulonglong2 whi = wp[1];
            fma2(acc[h2],p0,wlo.x); fma2(acc[h2],p1,wlo.y);
            fma2(acc[h2],p2,whi.x); fma2(acc[h2],p3,whi.y);
        }
    }
    float2 s2=up2(sum), q2=up2(ssq);
    float mean0=s2.x*(1.f/CZ), mean1=s2.y*(1.f/CZ);
    float rstd0=rsqrtf(q2.x*(1.f/CZ)-mean0*mean0+1e-5f);
    float rstd1=rsqrtf(q2.y*(1.f/CZ)-mean1*mean1+1e-5f);

    int b_ = (int)(t0>>20), q_ = (int)((t0>>10)&1023), k_ = (int)(t0&1023);
    size_t ob = (((size_t)b_*HH)*LL + q_)*LL + k_;    // k_ even, k_+1 same q
    #pragma unroll
    for(int h2=0;h2<8;h2++){
        int h = hbase + h2;
        float2 d = up2(acc[h2]);
        float v0 = rstd0*(d.x - mean0*wsum[h]);
        float v1 = rstd1*(d.y - mean1*wsum[h]);
        *(__half2*)&g_biash[ob + (size_t)h*LL*LL] = __floats2half2_rn(v0, v1);
    }
}

// -------------------- kernel 5: attention (2 q-rows x half-D per thread) --------------
__global__ __launch_bounds__(128) void attn_kernel(const int* __restrict__ mask)
{
    __shared__ __align__(16) float Ks[64*32];
    __shared__ __align__(16) float Vs[64*32];
    __shared__ __align__(16) __half bsh[128][72];   // 128 q-rows x 64 k (+pad)
    __shared__ float mk[64];

    int tid = threadIdx.x;           // 128
    int b = blockIdx.z, h = blockIdx.y;
    int q0 = blockIdx.x*128;
    int rg   = tid >> 1;             // 0..63 -> rows 2rg, 2rg+1
    int half = tid & 1;
    int r0 = q0 + rg*2;

    const float* qbase = g_q + (((size_t)(b*HH+h))*LL + r0)*DD + half*16;
    U64 qa[8], qb[8];
    #pragma unroll
    for(int i=0;i<4;i++){
        float4 t4 = ((const float4*)qbase)[i];
        qa[i*2]   = pk2(t4.x*SCALE, t4.y*SCALE);
        qa[i*2+1] = pk2(t4.z*SCALE, t4.w*SCALE);
        float4 u4 = ((const float4*)(qbase+DD))[i];
        qb[i*2]   = pk2(u4.x*SCALE, u4.y*SCALE);
        qb[i*2+1] = pk2(u4.z*SCALE, u4.w*SCALE);
    }
    U64 Oa[8], Ob[8];
    #pragma unroll
    for(int i=0;i<8;i++){ Oa[i]=0ull; Ob[i]=0ull; }
    float la=0.f, lb=0.f;

    const float* Kbase = g_k + ((size_t)(b*HH+h))*LL*DD;
    const float* Vbase = g_v + ((size_t)(b*HH+h))*LL*DD;
    const __half* bbase = g_biash + (((size_t)(b*HH+h))*LL + q0)*LL;

    for(int kt=0; kt<LL; kt+=64){
        __syncthreads();
        #pragma unroll
        for(int p=0;p<4;p++){
            int f = p*128 + tid;  // 512 float4s each
            ((float4*)Ks)[f] = ((const float4*)(Kbase + (size_t)kt*DD))[f];
            ((float4*)Vs)[f] = ((const float4*)(Vbase + (size_t)kt*DD))[f];
        }
        #pragma unroll
        for(int p=0;p<8;p++){
            int c = p*128 + tid;          // 1024 chunks of 8 halves
            int r = c>>3, part = c&7;
            *(float4*)&bsh[r][part*8] = ((const float4*)(bbase + (size_t)r*LL + kt))[part];
        }
        if(tid < 64) mk[tid] = mask[b*LL + kt + tid] ? 0.f : -10000.f;
        __syncthreads();

        #pragma unroll 2
        for(int j0=0;j0<64;j0+=2){
            float2 ba2 = __half22float2(*(const __half2*)&bsh[rg*2  ][j0]);
            float2 bb2 = __half22float2(*(const __half2*)&bsh[rg*2+1][j0]);
            float ba[2] = {ba2.x, ba2.y};
            float bbv[2]= {bb2.x, bb2.y};
            #pragma unroll
            for(int jj=0;jj<2;jj++){
                int j = j0 + jj;
                const ulonglong2* kp = (const ulonglong2*)&Ks[j*32 + half*16];
                ulonglong2 k0v = kp[0], k1v = kp[1];
                U64 sa=0ull, sb=0ull;
                fma2(sa,qa[0],k0v.x); fma2(sb,qb[0],k0v.x);
                fma2(sa,qa[1],k0v.y); fma2(sb,qb[1],k0v.y);
                fma2(sa,qa[2],k1v.x); fma2(sb,qb[2],k1v.x);
                fma2(sa,qa[3],k1v.y); fma2(sb,qb[3],k1v.y);
                ulonglong2 k2v = kp[2], k3v = kp[3];
                fma2(sa,qa[4],k2v.x); fma2(sb,qb[4],k2v.x);
                fma2(sa,qa[5],k2v.y); fma2(sb,qb[5],k2v.y);
                fma2(sa,qa[6],k3v.x); fma2(sb,qb[6],k3v.x);
                fma2(sa,qa[7],k3v.y); fma2(sb,qb[7],k3v.y);
                float2 fa = up2(sa), fb = up2(sb);
                float pa_ = fa.x + fa.y;
                float pb_ = fb.x + fb.y;
                pa_ += __shfl_xor_sync(0xffffffffu, pa_, 1);
                pb_ += __shfl_xor_sync(0xffffffffu, pb_, 1);
                float ea = __expf(pa_ + ba[jj]  + mk[j]);
                float eb = __expf(pb_ + bbv[jj] + mk[j]);
                la += ea; lb += eb;
                U64 ea2 = pk2(ea,ea), eb2 = pk2(eb,eb);
                const ulonglong2* vp = (const ulonglong2*)&Vs[j*32 + half*16];
                ulonglong2 v0v = vp[0], v1v = vp[1];
                fma2(Oa[0],ea2,v0v.x); fma2(Ob[0],eb2,v0v.x);
                fma2(Oa[1],ea2,v0v.y); fma2(Ob[1],eb2,v0v.y);
                fma2(Oa[2],ea2,v1v.x); fma2(Ob[2],eb2,v1v.x);
                fma2(Oa[3],ea2,v1v.y); fma2(Ob[3],eb2,v1v.y);
                ulonglong2 v2v = vp[2], v3v = vp[3];
                fma2(Oa[4],ea2,v2v.x); fma2(Ob[4],eb2,v2v.x);
                fma2(Oa[5],ea2,v2v.y); fma2(Ob[5],eb2,v2v.y);
                fma2(Oa[6],ea2,v3v.x); fma2(Ob[6],eb2,v3v.x);
                fma2(Oa[7],ea2,v3v.y); fma2(Ob[7],eb2,v3v.y);
            }
        }
    }
    float inva = 1.f/fmaxf(la, 1e-20f);
    float invb = 1.f/fmaxf(lb, 1e-20f);
    float* dsta = g_ao + ((size_t)(b*LL + r0))*CA + h*DD + half*16;
    float* dstb = dsta + CA;
    #pragma unroll
    for(int i=0;i<4;i++){
        float2 a0 = up2(Oa[i*2]), a1 = up2(Oa[i*2+1]);
        ((float4*)dsta)[i] = make_float4(a0.x*inva, a0.y*inva, a1.x*inva, a1.y*inva);
        float2 b0 = up2(Ob[i*2]), b1 = up2(Ob[i*2+1]);
        ((float4*)dstb)[i] = make_float4(b0.x*invb, b0.y*invb, b1.x*invb, b1.y*invb);
    }
}

// -------------------- kernel 6: output GEMM (f32x2) --------------------
__global__ __launch_bounds__(256) void out_kernel(
    const float* __restrict__ wo, const float* __restrict__ bo,
    const int* __restrict__ mask, float* __restrict__ out)
{
    const int K = CA;
    __shared__ __align__(16) float As[16][72];
    __shared__ __align__(16) float Bs[16][72];
    int tid = threadIdx.x;
    int tx = tid & 15, ty = tid >> 4;
    int m0 = blockIdx.y*64, n0 = blockIdx.x*64;
    U64 c[4][2]={};
    for(int k0=0;k0<K;k0+=16){
        #pragma unroll
        for(int p=0;p<4;p++){
            int e = p*256 + tid;
            int mm = e>>4, kk = e&15;
            size_t ai = (size_t)(m0+mm)*K + k0+kk;
            As[kk][mm] = sigm(g_g[ai]) * g_ao[ai];
            Bs[kk][mm] = wo[(size_t)(n0+mm)*K + k0+kk];
        }
        __syncthreads();
        #pragma unroll
        for(int kk=0;kk<16;kk++){
            float4 a4 = *(const float4*)&As[kk][ty*4];
            ulonglong2 bu = *(const ulonglong2*)&Bs[kk][tx*4];
            U64 ad[4];
            ad[0]=pk2(a4.x,a4.x); ad[1]=pk2(a4.y,a4.y); ad[2]=pk2(a4.z,a4.z); ad[3]=pk2(a4.w,a4.w);
            #pragma unroll
            for(int i=0;i<4;i++){
                fma2(c[i][0],ad[i],bu.x);
                fma2(c[i][1],ad[i],bu.y);
            }
        }
        __syncthreads();
    }
    #pragma unroll
    for(int i=0;i<4;i++){
        int m = m0 + ty*4 + i;
        float mq = mask[m] ? 1.f : 0.f;
        #pragma unroll
        for(int jp=0;jp<2;jp++){
            float2 v = up2(c[i][jp]);
            int n = n0 + tx*4 + jp*2;
            out[(size_t)m*CA + n]   = (v.x + bo[n])   * g_glast[(size_t)m*CA + n]   * mq;
            out[(size_t)m*CA + n+1] = (v.y + bo[n+1]) * g_glast[(size_t)m*CA + n+1] * mq;
        }
    }
}

// -------------------- launch --------------------
extern "C" void kernel_launch(void* const* d_in, const int* in_sizes, int n_in,
                              void* d_out, int out_size)
{
    const float* a          = (const float*)d_in[0];
    const float* s          = (const float*)d_in[1];
    const float* z          = (const float*)d_in[2];
    const float* ln_s_scale = (const float*)d_in[3];
    const float* ada_w_s    = (const float*)d_in[4];
    const float* ada_b_s    = (const float*)d_in[5];
    const float* ada_w_nb   = (const float*)d_in[6];
    const float* wq = (const float*)d_in[7];  const float* bq = (const float*)d_in[8];
    const float* wk = (const float*)d_in[9];  const float* bk = (const float*)d_in[10];
    const float* wv = (const float*)d_in[11]; const float* bv = (const float*)d_in[12];
    const float* wg = (const float*)d_in[13]; const float* bg = (const float*)d_in[14];
    const float* wo = (const float*)d_in[15]; const float* bo = (const float*)d_in[16];
    const float* ln_z_scale = (const float*)d_in[17];
    const float* wz         = (const float*)d_in[18];
    const float* w_last     = (const float*)d_in[19];
    const float* b_last     = (const float*)d_in[20];
    const int*   mask       = (const int*)d_in[21];
    float* out = (float*)d_out;

    ln_kernel<<<MM, 256>>>(a, s, ln_s_scale);
    anorm_kernel<<<dim3(CA/64, MM/64), 256>>>(s, ada_w_s, ada_b_s, ada_w_nb, w_last, b_last);
    qkvg_kernel<<<dim3(2048/128, MM/128), 256>>>(wq,bq, wk,bk, wv,bv, wg,bg);
    bias_kernel<<<(BB*LL*LL)/256, 256>>>(z, ln_z_scale, wz);
    attn_kernel<<<dim3(LL/128, HH, BB), 128>>>(mask);
    out_kernel<<<dim3(CA/64, MM/64), 256>>>(wo, bo, mask, out);
}

// round 6
// speedup vs baseline: 1.0853x; 1.0853x over previous
#include <cuda_runtime.h>
#include <cuda_bf16.h>
#include <cuda_fp16.h>

// Problem constants
#define BB 2
#define LL 1024
#define CA 512
#define CS 384
#define CZ 64
#define HH 16
#define DD 32
#define MM (BB*LL)          // 2048 rows
#define SCALE 0.17677669529663687f  // 1/sqrt(32)

typedef unsigned long long U64;
__device__ __forceinline__ U64 pk2(float lo, float hi){ U64 r; asm("mov.b64 %0, {%1,%2};":"=l"(r):"f"(lo),"f"(hi)); return r; }
__device__ __forceinline__ void fma2(U64 &d, U64 a, U64 b){ asm("fma.rn.f32x2 %0, %1, %2, %3;":"=l"(d):"l"(a),"l"(b),"l"(d)); }
__device__ __forceinline__ float2 up2(U64 v){ float2 r; asm("mov.b64 {%0,%1}, %2;":"=f"(r.x),"=f"(r.y):"l"(v)); return r; }

// -------------------- device scratch --------------------
__device__ __align__(16) float g_s_ln[MM*CS];
__device__ __align__(16) float g_a_ln[MM*CA];
__device__ __align__(16) float g_anorm[MM*CA];
__device__ __align__(16) float g_glast[MM*CA];
__device__ __align__(16) float g_q[MM*CA];   // [b][h][l][d]
__device__ __align__(16) float g_k[MM*CA];
__device__ __align__(16) float g_v[MM*CA];
__device__ __align__(16) float g_g[MM*CA];   // pre-sigmoid gate
__device__ __align__(16) float g_ao[MM*CA];  // attention out [b][l][h*32+d]
__device__ __align__(16) __half g_biash[(size_t)BB*HH*LL*LL]; // 67MB fp16 bias

__device__ __forceinline__ float sigm(float x){ return 1.f/(1.f+__expf(-x)); }

// -------------------- kernel 1: row layernorms --------------------
__global__ __launch_bounds__(256) void ln_kernel(
    const float* __restrict__ a, const float* __restrict__ s,
    const float* __restrict__ s_scale)
{
    int row = blockIdx.x;
    int tid = threadIdx.x;
    __shared__ float rs[16];
    const float* ar = a + (size_t)row*CA;
    float x0 = ar[tid], x1 = ar[tid+256];
    float sum = x0+x1, ss = x0*x0 + x1*x1;
    #pragma unroll
    for(int o=16;o;o>>=1){ sum += __shfl_xor_sync(0xffffffffu,sum,o); ss += __shfl_xor_sync(0xffffffffu,ss,o); }
    if((tid&31)==0){ rs[tid>>5]=sum; rs[8+(tid>>5)]=ss; }
    __syncthreads();
    if(tid==0){ float S=0,Q=0; for(int i=0;i<8;i++){S+=rs[i];Q+=rs[8+i];} rs[0]=S; rs[8]=Q; }
    __syncthreads();
    float mean = rs[0]*(1.f/CA);
    float var  = rs[8]*(1.f/CA) - mean*mean;
    float rstd = rsqrtf(var + 1e-5f);
    g_a_ln[(size_t)row*CA + tid]      = (x0-mean)*rstd;
    g_a_ln[(size_t)row*CA + tid+256]  = (x1-mean)*rstd;
    __syncthreads();
    const float* sr = s + (size_t)row*CS;
    float y0 = sr[tid];
    float y1 = (tid < CS-256) ? sr[tid+256] : 0.f;
    sum = y0+y1; ss = y0*y0 + y1*y1;
    #pragma unroll
    for(int o=16;o;o>>=1){ sum += __shfl_xor_sync(0xffffffffu,sum,o); ss += __shfl_xor_sync(0xffffffffu,ss,o); }
    if((tid&31)==0){ rs[tid>>5]=sum; rs[8+(tid>>5)]=ss; }
    __syncthreads();
    if(tid==0){ float S=0,Q=0; for(int i=0;i<8;i++){S+=rs[i];Q+=rs[8+i];} rs[0]=S; rs[8]=Q; }
    __syncthreads();
    mean = rs[0]*(1.f/CS);
    var  = rs[8]*(1.f/CS) - mean*mean;
    rstd = rsqrtf(var + 1e-5f);
    g_s_ln[(size_t)row*CS + tid] = (y0-mean)*rstd*s_scale[tid];
    if(tid < CS-256)
        g_s_ln[(size_t)row*CS + tid+256] = (y1-mean)*rstd*s_scale[tid+256];
}

// -------------------- kernel 2: a_norm + glast (triple GEMM, f32x2) --------------------
__global__ __launch_bounds__(256) void anorm_kernel(
    const float* __restrict__ s_raw,
    const float* __restrict__ ada_w_s, const float* __restrict__ ada_b_s,
    const float* __restrict__ ada_w_nb,
    const float* __restrict__ w_last, const float* __restrict__ b_last)
{
    const int K = CS;
    __shared__ __align__(16) float As1[16][72];
    __shared__ __align__(16) float As2[16][72];
    __shared__ __align__(16) float Bs1[16][72];
    __shared__ __align__(16) float Bs2[16][72];
    __shared__ __align__(16) float Bs3[16][72];
    int tid = threadIdx.x;
    int tx = tid & 15, ty = tid >> 4;
    int m0 = blockIdx.y*64, n0 = blockIdx.x*64;
    U64 c1[4][2]={}, c2[4][2]={}, c3[4][2]={};
    for(int k0=0;k0<K;k0+=16){
        #pragma unroll
        for(int p=0;p<4;p++){
            int e = p*256 + tid;
            int mm = e>>4, kk = e&15;
            As1[kk][mm] = g_s_ln[(size_t)(m0+mm)*K + k0+kk];
            As2[kk][mm] = s_raw[(size_t)(m0+mm)*K + k0+kk];
            Bs1[kk][mm] = ada_w_s [(size_t)(n0+mm)*K + k0+kk];
            Bs2[kk][mm] = ada_w_nb[(size_t)(n0+mm)*K + k0+kk];
            Bs3[kk][mm] = w_last  [(size_t)(n0+mm)*K + k0+kk];
        }
        __syncthreads();
        #pragma unroll
        for(int kk=0;kk<16;kk++){
            float4 a1 = *(const float4*)&As1[kk][ty*4];
            float4 a2 = *(const float4*)&As2[kk][ty*4];
            ulonglong2 b1 = *(const ulonglong2*)&Bs1[kk][tx*4];
            ulonglong2 b2 = *(const ulonglong2*)&Bs2[kk][tx*4];
            ulonglong2 b3 = *(const ulonglong2*)&Bs3[kk][tx*4];
            U64 a1d[4], a2d[4];
            a1d[0]=pk2(a1.x,a1.x); a1d[1]=pk2(a1.y,a1.y); a1d[2]=pk2(a1.z,a1.z); a1d[3]=pk2(a1.w,a1.w);
            a2d[0]=pk2(a2.x,a2.x); a2d[1]=pk2(a2.y,a2.y); a2d[2]=pk2(a2.z,a2.z); a2d[3]=pk2(a2.w,a2.w);
            #pragma unroll
            for(int i=0;i<4;i++){
                fma2(c1[i][0],a1d[i],b1.x); fma2(c1[i][1],a1d[i],b1.y);
                fma2(c2[i][0],a1d[i],b2.x); fma2(c2[i][1],a1d[i],b2.y);
                fma2(c3[i][0],a2d[i],b3.x); fma2(c3[i][1],a2d[i],b3.y);
            }
        }
        __syncthreads();
    }
    #pragma unroll
    for(int i=0;i<4;i++){
        int m = m0 + ty*4 + i;
        #pragma unroll
        for(int jp=0;jp<2;jp++){
            float2 v1 = up2(c1[i][jp]), v2 = up2(c2[i][jp]), v3 = up2(c3[i][jp]);
            int n = n0 + tx*4 + jp*2;
            float sgA = sigm(v1.x + ada_b_s[n]);
            float sgB = sigm(v1.y + ada_b_s[n+1]);
            g_anorm[(size_t)m*CA + n]   = sgA * g_a_ln[(size_t)m*CA + n]   + v2.x;
            g_anorm[(size_t)m*CA + n+1] = sgB * g_a_ln[(size_t)m*CA + n+1] + v2.y;
            g_glast[(size_t)m*CA + n]   = sigm(v3.x + b_last[n]);
            g_glast[(size_t)m*CA + n+1] = sigm(v3.y + b_last[n+1]);
        }
    }
}

// -------------------- kernel 3: QKVG projections (f32x2) --------------------
__global__ __launch_bounds__(256) void qkvg_kernel(
    const float* __restrict__ wq, const float* __restrict__ bq,
    const float* __restrict__ wk, const float* __restrict__ bk,
    const float* __restrict__ wv, const float* __restrict__ bv,
    const float* __restrict__ wg, const float* __restrict__ bg)
{
    const int K = CA;
    __shared__ __align__(16) float As[16][136];
    __shared__ __align__(16) float Bs[16][136];
    int tid = threadIdx.x;
    int tx = tid & 15, ty = tid >> 4;
    int m0 = blockIdx.y*128;
    int n0 = blockIdx.x*128;
    int which = n0 >> 9;
    int nn0 = n0 & 511;
    const float* W  = (which==0)?wq : (which==1)?wk : (which==2)?wv : wg;
    const float* Bv = (which==0)?bq : (which==1)?bk : (which==2)?bv : bg;
    U64 c[8][4]={};
    for(int k0=0;k0<K;k0+=16){
        #pragma unroll
        for(int p=0;p<8;p++){
            int e = p*256 + tid;
            int mm = e>>4, kk = e&15;
            As[kk][mm] = g_anorm[(size_t)(m0+mm)*K + k0+kk];
            Bs[kk][mm] = W[(size_t)(nn0+mm)*K + k0+kk];
        }
        __syncthreads();
        #pragma unroll
        for(int kk=0;kk<16;kk++){
            float4 t0 = *(const float4*)&As[kk][ty*8];
            float4 t1 = *(const float4*)&As[kk][ty*8+4];
            ulonglong2 b0 = *(const ulonglong2*)&Bs[kk][tx*8];
            ulonglong2 b1 = *(const ulonglong2*)&Bs[kk][tx*8+4];
            U64 ad[8];
            ad[0]=pk2(t0.x,t0.x); ad[1]=pk2(t0.y,t0.y); ad[2]=pk2(t0.z,t0.z); ad[3]=pk2(t0.w,t0.w);
            ad[4]=pk2(t1.x,t1.x); ad[5]=pk2(t1.y,t1.y); ad[6]=pk2(t1.z,t1.z); ad[7]=pk2(t1.w,t1.w);
            #pragma unroll
            for(int i=0;i<8;i++){
                fma2(c[i][0],ad[i],b0.x); fma2(c[i][1],ad[i],b0.y);
                fma2(c[i][2],ad[i],b1.x); fma2(c[i][3],ad[i],b1.y);
            }
        }
        __syncthreads();
    }
    float* dst = (which==0)?g_q : (which==1)?g_k : g_v;
    #pragma unroll
    for(int i=0;i<8;i++){
        int m = m0 + ty*8 + i;
        #pragma unroll
        for(int jp=0;jp<4;jp++){
            float2 v = up2(c[i][jp]);
            #pragma unroll
            for(int l=0;l<2;l++){
                int nn = nn0 + tx*8 + jp*2 + l;
                float val = (l?v.y:v.x) + Bv[nn];
                if(which < 3){
                    int hh = nn>>5, dd2 = nn&31;
                    int bb = m>>10, ll = m&1023;
                    dst[(((size_t)(bb*HH+hh))*LL + ll)*DD + dd2] = val;
                } else {
                    g_g[(size_t)m*CA + nn] = val;
                }
            }
        }
    }
}

// -------------------- kernel 4: pair bias v5 --------------------
// blockIdx.y selects head half (constant smem offsets). Each thread: 4 consecutive
// k-rows (2 packed row-pairs) x 8 heads. Each weight LDS.128 feeds 4 fma2.
__global__ __launch_bounds__(256) void bias_kernel(
    const float* __restrict__ z, const float* __restrict__ z_scale,
    const float* __restrict__ wz)
{
    __shared__ __align__(16) U64 wzs2[8][CZ];   // (w,w) packed for my 8 heads, 4KB
    __shared__ float wsum[8];
    int tid = threadIdx.x;
    int hbase = blockIdx.y * 8;
    for(int e=tid;e<8*CZ;e+=256){
        int h = e>>6, c = e&63;
        float w = wz[(hbase+h)*CZ + c]*z_scale[c];
        wzs2[h][c] = pk2(w,w);
    }
    __syncthreads();
    if(tid < 8){ float S=0.f; for(int c=0;c<CZ;c++){ S += up2(wzs2[tid][c]).x; } wsum[tid]=S; }
    __syncthreads();

    size_t t0 = ((size_t)blockIdx.x*256 + tid)*4;   // 4 consecutive z rows (same b,q)
    const float4* zp = (const float4*)(z + t0*CZ);

    U64 accA[8], accB[8];
    #pragma unroll
    for(int h=0;h<8;h++){ accA[h]=0ull; accB[h]=0ull; }
    U64 sumA=0ull, ssqA=0ull, sumB=0ull, ssqB=0ull;
    const U64 one2 = pk2(1.f,1.f);

    #pragma unroll
    for(int cs=0;cs<16;cs++){
        float4 a = zp[cs];
        float4 b = zp[16+cs];
        float4 c = zp[32+cs];
        float4 d = zp[48+cs];
        U64 pA0=pk2(a.x,b.x), pA1=pk2(a.y,b.y), pA2=pk2(a.z,b.z), pA3=pk2(a.w,b.w);
        U64 pB0=pk2(c.x,d.x), pB1=pk2(c.y,d.y), pB2=pk2(c.z,d.z), pB3=pk2(c.w,d.w);
        fma2(sumA,pA0,one2); fma2(sumA,pA1,one2); fma2(sumA,pA2,one2); fma2(sumA,pA3,one2);
        fma2(ssqA,pA0,pA0);  fma2(ssqA,pA1,pA1);  fma2(ssqA,pA2,pA2);  fma2(ssqA,pA3,pA3);
        fma2(sumB,pB0,one2); fma2(sumB,pB1,one2); fma2(sumB,pB2,one2); fma2(sumB,pB3,one2);
        fma2(ssqB,pB0,pB0);  fma2(ssqB,pB1,pB1);  fma2(ssqB,pB2,pB2);  fma2(ssqB,pB3,pB3);
        #pragma unroll
        for(int h=0;h<8;h++){
            ulonglong2 wlo = *(const ulonglong2*)&wzs2[h][cs*4];
            ulonglong2 whi = *(const ulonglong2*)&wzs2[h][cs*4+2];
            fma2(accA[h],pA0,wlo.x); fma2(accA[h],pA1,wlo.y);
            fma2(accA[h],pA2,whi.x); fma2(accA[h],pA3,whi.y);
            fma2(accB[h],pB0,wlo.x); fma2(accB[h],pB1,wlo.y);
            fma2(accB[h],pB2,whi.x); fma2(accB[h],pB3,whi.y);
        }
    }
    float2 sA=up2(sumA), qA=up2(ssqA), sB=up2(sumB), qB=up2(ssqB);
    float mean0=sA.x*(1.f/CZ), mean1=sA.y*(1.f/CZ);
    float mean2=sB.x*(1.f/CZ), mean3=sB.y*(1.f/CZ);
    float rstd0=rsqrtf(qA.x*(1.f/CZ)-mean0*mean0+1e-5f);
    float rstd1=rsqrtf(qA.y*(1.f/CZ)-mean1*mean1+1e-5f);
    float rstd2=rsqrtf(qB.x*(1.f/CZ)-mean2*mean2+1e-5f);
    float rstd3=rsqrtf(qB.y*(1.f/CZ)-mean3*mean3+1e-5f);

    int b_ = (int)(t0>>20), q_ = (int)((t0>>10)&1023), k_ = (int)(t0&1023);
    size_t ob = (((size_t)(b_*HH + hbase))*LL + q_)*LL + k_;   // k_ 4-aligned
    #pragma unroll
    for(int h=0;h<8;h++){
        float2 dA = up2(accA[h]);
        float2 dB = up2(accB[h]);
        float ws = wsum[h];
        __half2 h01 = __floats2half2_rn(rstd0*(dA.x - mean0*ws), rstd1*(dA.y - mean1*ws));
        __half2 h23 = __floats2half2_rn(rstd2*(dB.x - mean2*ws), rstd3*(dB.y - mean3*ws));
        uint2 u;
        u.x = *(unsigned*)&h01;
        u.y = *(unsigned*)&h23;
        *(uint2*)&g_biash[ob + (size_t)h*LL*LL] = u;
    }
}

// -------------------- kernel 5: attention (round-3 version) --------------------
__global__ __launch_bounds__(128) void attn_kernel(const int* __restrict__ mask)
{
    __shared__ __align__(16) float Ks[64*32];
    __shared__ __align__(16) float Vs[64*32];
    __shared__ __align__(16) __half bsh[64][80];
    __shared__ float mk[64];

    int tid = threadIdx.x;          // 128
    int b = blockIdx.z, h = blockIdx.y;
    int q0 = blockIdx.x*64;
    int row = tid >> 1;             // 0..63
    int half = tid & 1;             // which 16-d half

    const float* qp = g_q + (((size_t)(b*HH+h))*LL + q0+row)*DD + half*16;
    U64 qr2[8];
    #pragma unroll
    for(int i=0;i<4;i++){
        float4 t4 = ((const float4*)qp)[i];
        qr2[i*2]   = pk2(t4.x*SCALE, t4.y*SCALE);
        qr2[i*2+1] = pk2(t4.z*SCALE, t4.w*SCALE);
    }
    U64 O2[8];
    #pragma unroll
    for(int i=0;i<8;i++) O2[i]=0ull;
    float lrun = 0.f;

    const float* Kbase = g_k + ((size_t)(b*HH+h))*LL*DD;
    const float* Vbase = g_v + ((size_t)(b*HH+h))*LL*DD;
    const __half* bbase = g_biash + (((size_t)(b*HH+h))*LL + q0)*LL;

    for(int kt=0; kt<LL; kt+=64){
        __syncthreads();
        #pragma unroll
        for(int p=0;p<4;p++){
            int f = p*128 + tid;  // 512 float4s
            ((float4*)Ks)[f] = ((const float4*)(Kbase + (size_t)kt*DD))[f];
            ((float4*)Vs)[f] = ((const float4*)(Vbase + (size_t)kt*DD))[f];
        }
        #pragma unroll
        for(int p=0;p<4;p++){
            int c = p*128 + tid;   // 512 chunks of 8 halves
            int r = c>>3, part = c&7;
            *(float4*)&bsh[r][part*8] = ((const float4*)(bbase + (size_t)r*LL + kt))[part];
        }
        if(tid < 64) mk[tid] = mask[b*LL + kt + tid] ? 0.f : -10000.f;
        __syncthreads();

        #pragma unroll 2
        for(int j0=0;j0<64;j0+=4){
            const __half2* bp = (const __half2*)&bsh[row][j0];
            float2 b01 = __half22float2(bp[0]);
            float2 b23 = __half22float2(bp[1]);
            float bb4[4] = {b01.x, b01.y, b23.x, b23.y};
            #pragma unroll
            for(int jj=0;jj<4;jj++){
                int j = j0 + jj;
                const ulonglong2* kp = (const ulonglong2*)&Ks[j*32 + half*16];
                U64 sacc = 0ull;
                #pragma unroll
                for(int i=0;i<4;i++){
                    ulonglong2 kv = kp[i];
                    fma2(sacc, qr2[i*2],   kv.x);
                    fma2(sacc, qr2[i*2+1], kv.y);
                }
                float2 sp = up2(sacc);
                float part = sp.x + sp.y;
                float tot = part + __shfl_xor_sync(0xffffffffu, part, 1);
                float s_ = tot + bb4[jj] + mk[j];
                float p_ = __expf(s_);
                lrun += p_;
                U64 pp = pk2(p_, p_);
                const ulonglong2* vp = (const ulonglong2*)&Vs[j*32 + half*16];
                #pragma unroll
                for(int i=0;i<4;i++){
                    ulonglong2 vv = vp[i];
                    fma2(O2[i*2],   pp, vv.x);
                    fma2(O2[i*2+1], pp, vv.y);
                }
            }
        }
    }
    float inv = 1.f/fmaxf(lrun, 1e-20f);
    float* dst = g_ao + ((size_t)(b*LL + q0+row))*CA + h*DD + half*16;
    #pragma unroll
    for(int i=0;i<4;i++){
        float2 v0 = up2(O2[i*2]), v1 = up2(O2[i*2+1]);
        ((float4*)dst)[i] = make_float4(v0.x*inv, v0.y*inv, v1.x*inv, v1.y*inv);
    }
}

// -------------------- kernel 6: output GEMM (f32x2) --------------------
__global__ __launch_bounds__(256) void out_kernel(
    const float* __restrict__ wo, const float* __restrict__ bo,
    const int* __restrict__ mask, float* __restrict__ out)
{
    const int K = CA;
    __shared__ __align__(16) float As[16][72];
    __shared__ __align__(16) float Bs[16][72];
    int tid = threadIdx.x;
    int tx = tid & 15, ty = tid >> 4;
    int m0 = blockIdx.y*64, n0 = blockIdx.x*64;
    U64 c[4][2]={};
    for(int k0=0;k0<K;k0+=16){
        #pragma unroll
        for(int p=0;p<4;p++){
            int e = p*256 + tid;
            int mm = e>>4, kk = e&15;
            size_t ai = (size_t)(m0+mm)*K + k0+kk;
            As[kk][mm] = sigm(g_g[ai]) * g_ao[ai];
            Bs[kk][mm] = wo[(size_t)(n0+mm)*K + k0+kk];
        }
        __syncthreads();
        #pragma unroll
        for(int kk=0;kk<16;kk++){
            float4 a4 = *(const float4*)&As[kk][ty*4];
            ulonglong2 bu = *(const ulonglong2*)&Bs[kk][tx*4];
            U64 ad[4];
            ad[0]=pk2(a4.x,a4.x); ad[1]=pk2(a4.y,a4.y); ad[2]=pk2(a4.z,a4.z); ad[3]=pk2(a4.w,a4.w);
            #pragma unroll
            for(int i=0;i<4;i++){
                fma2(c[i][0],ad[i],bu.x);
                fma2(c[i][1],ad[i],bu.y);
            }
        }
        __syncthreads();
    }
    #pragma unroll
    for(int i=0;i<4;i++){
        int m = m0 + ty*4 + i;
        float mq = mask[m] ? 1.f : 0.f;
        #pragma unroll
        for(int jp=0;jp<2;jp++){
            float2 v = up2(c[i][jp]);
            int n = n0 + tx*4 + jp*2;
            out[(size_t)m*CA + n]   = (v.x + bo[n])   * g_glast[(size_t)m*CA + n]   * mq;
            out[(size_t)m*CA + n+1] = (v.y + bo[n+1]) * g_glast[(size_t)m*CA + n+1] * mq;
        }
    }
}

// -------------------- launch --------------------
extern "C" void kernel_launch(void* const* d_in, const int* in_sizes, int n_in,
                              void* d_out, int out_size)
{
    const float* a          = (const float*)d_in[0];
    const float* s          = (const float*)d_in[1];
    const float* z          = (const float*)d_in[2];
    const float* ln_s_scale = (const float*)d_in[3];
    const float* ada_w_s    = (const float*)d_in[4];
    const float* ada_b_s    = (const float*)d_in[5];
    const float* ada_w_nb   = (const float*)d_in[6];
    const float* wq = (const float*)d_in[7];  const float* bq = (const float*)d_in[8];
    const float* wk = (const float*)d_in[9];  const float* bk = (const float*)d_in[10];
    const float* wv = (const float*)d_in[11]; const float* bv = (const float*)d_in[12];
    const float* wg = (const float*)d_in[13]; const float* bg = (const float*)d_in[14];
    const float* wo = (const float*)d_in[15]; const float* bo = (const float*)d_in[16];
    const float* ln_z_scale = (const float*)d_in[17];
    const float* wz         = (const float*)d_in[18];
    const float* w_last     = (const float*)d_in[19];
    const float* b_last     = (const float*)d_in[20];
    const int*   mask       = (const int*)d_in[21];
    float* out = (float*)d_out;

    ln_kernel<<<MM, 256>>>(a, s, ln_s_scale);
    anorm_kernel<<<dim3(CA/64, MM/64), 256>>>(s, ada_w_s, ada_b_s, ada_w_nb, w_last, b_last);
    qkvg_kernel<<<dim3(2048/128, MM/128), 256>>>(wq,bq, wk,bk, wv,bv, wg,bg);
    bias_kernel<<<dim3((BB*LL*LL)/1024, 2), 256>>>(z, ln_z_scale, wz);
    attn_kernel<<<dim3(LL/64, HH, BB), 128>>>(mask);
    out_kernel<<<dim3(CA/64, MM/64), 256>>>(wo, bo, mask, out);
}

// round 7
// speedup vs baseline: 1.2024x; 1.1079x over previous
#include <cuda_runtime.h>
#include <cuda_bf16.h>
#include <cuda_fp16.h>

// Problem constants
#define BB 2
#define LL 1024
#define CA 512
#define CS 384
#define CZ 64
#define HH 16
#define DD 32
#define MM (BB*LL)          // 2048 rows
#define SCALE 0.17677669529663687f  // 1/sqrt(32)

typedef unsigned long long U64;
__device__ __forceinline__ U64 pk2(float lo, float hi){ U64 r; asm("mov.b64 %0, {%1,%2};":"=l"(r):"f"(lo),"f"(hi)); return r; }
__device__ __forceinline__ void fma2(U64 &d, U64 a, U64 b){ asm("fma.rn.f32x2 %0, %1, %2, %3;":"=l"(d):"l"(a),"l"(b),"l"(d)); }
__device__ __forceinline__ float2 up2(U64 v){ float2 r; asm("mov.b64 {%0,%1}, %2;":"=f"(r.x),"=f"(r.y):"l"(v)); return r; }

// -------------------- device scratch --------------------
__device__ __align__(16) float g_s_ln[MM*CS];
__device__ __align__(16) float g_a_ln[MM*CA];
__device__ __align__(16) float g_anorm[MM*CA];
__device__ __align__(16) float g_glast[MM*CA];
__device__ __align__(16) float g_q[MM*CA];   // [b][h][l][d]
__device__ __align__(16) float g_k[MM*CA];
__device__ __align__(16) float g_v[MM*CA];
__device__ __align__(16) float g_g[MM*CA];   // pre-sigmoid gate
__device__ __align__(16) float g_ao[MM*CA];  // attention out [b][l][h*32+d]
__device__ __align__(16) __half g_biash[(size_t)BB*HH*LL*LL]; // 67MB fp16 bias

__device__ __forceinline__ float sigm(float x){ return 1.f/(1.f+__expf(-x)); }

// -------------------- kernel 1: row layernorms --------------------
__global__ __launch_bounds__(256) void ln_kernel(
    const float* __restrict__ a, const float* __restrict__ s,
    const float* __restrict__ s_scale)
{
    int row = blockIdx.x;
    int tid = threadIdx.x;
    __shared__ float rs[16];
    const float* ar = a + (size_t)row*CA;
    float x0 = ar[tid], x1 = ar[tid+256];
    float sum = x0+x1, ss = x0*x0 + x1*x1;
    #pragma unroll
    for(int o=16;o;o>>=1){ sum += __shfl_xor_sync(0xffffffffu,sum,o); ss += __shfl_xor_sync(0xffffffffu,ss,o); }
    if((tid&31)==0){ rs[tid>>5]=sum; rs[8+(tid>>5)]=ss; }
    __syncthreads();
    if(tid==0){ float S=0,Q=0; for(int i=0;i<8;i++){S+=rs[i];Q+=rs[8+i];} rs[0]=S; rs[8]=Q; }
    __syncthreads();
    float mean = rs[0]*(1.f/CA);
    float var  = rs[8]*(1.f/CA) - mean*mean;
    float rstd = rsqrtf(var + 1e-5f);
    g_a_ln[(size_t)row*CA + tid]      = (x0-mean)*rstd;
    g_a_ln[(size_t)row*CA + tid+256]  = (x1-mean)*rstd;
    __syncthreads();
    const float* sr = s + (size_t)row*CS;
    float y0 = sr[tid];
    float y1 = (tid < CS-256) ? sr[tid+256] : 0.f;
    sum = y0+y1; ss = y0*y0 + y1*y1;
    #pragma unroll
    for(int o=16;o;o>>=1){ sum += __shfl_xor_sync(0xffffffffu,sum,o); ss += __shfl_xor_sync(0xffffffffu,ss,o); }
    if((tid&31)==0){ rs[tid>>5]=sum; rs[8+(tid>>5)]=ss; }
    __syncthreads();
    if(tid==0){ float S=0,Q=0; for(int i=0;i<8;i++){S+=rs[i];Q+=rs[8+i];} rs[0]=S; rs[8]=Q; }
    __syncthreads();
    mean = rs[0]*(1.f/CS);
    var  = rs[8]*(1.f/CS) - mean*mean;
    rstd = rsqrtf(var + 1e-5f);
    g_s_ln[(size_t)row*CS + tid] = (y0-mean)*rstd*s_scale[tid];
    if(tid < CS-256)
        g_s_ln[(size_t)row*CS + tid+256] = (y1-mean)*rstd*s_scale[tid+256];
}

// -------------------- kernel 2: a_norm + glast (triple GEMM, f32x2) --------------------
__global__ __launch_bounds__(256) void anorm_kernel(
    const float* __restrict__ s_raw,
    const float* __restrict__ ada_w_s, const float* __restrict__ ada_b_s,
    const float* __restrict__ ada_w_nb,
    const float* __restrict__ w_last, const float* __restrict__ b_last)
{
    const int K = CS;
    __shared__ __align__(16) float As1[16][72];
    __shared__ __align__(16) float As2[16][72];
    __shared__ __align__(16) float Bs1[16][72];
    __shared__ __align__(16) float Bs2[16][72];
    __shared__ __align__(16) float Bs3[16][72];
    int tid = threadIdx.x;
    int tx = tid & 15, ty = tid >> 4;
    int m0 = blockIdx.y*64, n0 = blockIdx.x*64;
    U64 c1[4][2]={}, c2[4][2]={}, c3[4][2]={};
    for(int k0=0;k0<K;k0+=16){
        #pragma unroll
        for(int p=0;p<4;p++){
            int e = p*256 + tid;
            int mm = e>>4, kk = e&15;
            As1[kk][mm] = g_s_ln[(size_t)(m0+mm)*K + k0+kk];
            As2[kk][mm] = s_raw[(size_t)(m0+mm)*K + k0+kk];
            Bs1[kk][mm] = ada_w_s [(size_t)(n0+mm)*K + k0+kk];
            Bs2[kk][mm] = ada_w_nb[(size_t)(n0+mm)*K + k0+kk];
            Bs3[kk][mm] = w_last  [(size_t)(n0+mm)*K + k0+kk];
        }
        __syncthreads();
        #pragma unroll
        for(int kk=0;kk<16;kk++){
            float4 a1 = *(const float4*)&As1[kk][ty*4];
            float4 a2 = *(const float4*)&As2[kk][ty*4];
            ulonglong2 b1 = *(const ulonglong2*)&Bs1[kk][tx*4];
            ulonglong2 b2 = *(const ulonglong2*)&Bs2[kk][tx*4];
            ulonglong2 b3 = *(const ulonglong2*)&Bs3[kk][tx*4];
            U64 a1d[4], a2d[4];
            a1d[0]=pk2(a1.x,a1.x); a1d[1]=pk2(a1.y,a1.y); a1d[2]=pk2(a1.z,a1.z); a1d[3]=pk2(a1.w,a1.w);
            a2d[0]=pk2(a2.x,a2.x); a2d[1]=pk2(a2.y,a2.y); a2d[2]=pk2(a2.z,a2.z); a2d[3]=pk2(a2.w,a2.w);
            #pragma unroll
            for(int i=0;i<4;i++){
                fma2(c1[i][0],a1d[i],b1.x); fma2(c1[i][1],a1d[i],b1.y);
                fma2(c2[i][0],a1d[i],b2.x); fma2(c2[i][1],a1d[i],b2.y);
                fma2(c3[i][0],a2d[i],b3.x); fma2(c3[i][1],a2d[i],b3.y);
            }
        }
        __syncthreads();
    }
    #pragma unroll
    for(int i=0;i<4;i++){
        int m = m0 + ty*4 + i;
        #pragma unroll
        for(int jp=0;jp<2;jp++){
            float2 v1 = up2(c1[i][jp]), v2 = up2(c2[i][jp]), v3 = up2(c3[i][jp]);
            int n = n0 + tx*4 + jp*2;
            float sgA = sigm(v1.x + ada_b_s[n]);
            float sgB = sigm(v1.y + ada_b_s[n+1]);
            g_anorm[(size_t)m*CA + n]   = sgA * g_a_ln[(size_t)m*CA + n]   + v2.x;
            g_anorm[(size_t)m*CA + n+1] = sgB * g_a_ln[(size_t)m*CA + n+1] + v2.y;
            g_glast[(size_t)m*CA + n]   = sigm(v3.x + b_last[n]);
            g_glast[(size_t)m*CA + n+1] = sigm(v3.y + b_last[n+1]);
        }
    }
}

// -------------------- kernel 3: QKVG projections (f32x2) --------------------
__global__ __launch_bounds__(256) void qkvg_kernel(
    const float* __restrict__ wq, const float* __restrict__ bq,
    const float* __restrict__ wk, const float* __restrict__ bk,
    const float* __restrict__ wv, const float* __restrict__ bv,
    const float* __restrict__ wg, const float* __restrict__ bg)
{
    const int K = CA;
    __shared__ __align__(16) float As[16][136];
    __shared__ __align__(16) float Bs[16][136];
    int tid = threadIdx.x;
    int tx = tid & 15, ty = tid >> 4;
    int m0 = blockIdx.y*128;
    int n0 = blockIdx.x*128;
    int which = n0 >> 9;
    int nn0 = n0 & 511;
    const float* W  = (which==0)?wq : (which==1)?wk : (which==2)?wv : wg;
    const float* Bv = (which==0)?bq : (which==1)?bk : (which==2)?bv : bg;
    U64 c[8][4]={};
    for(int k0=0;k0<K;k0+=16){
        #pragma unroll
        for(int p=0;p<8;p++){
            int e = p*256 + tid;
            int mm = e>>4, kk = e&15;
            As[kk][mm] = g_anorm[(size_t)(m0+mm)*K + k0+kk];
            Bs[kk][mm] = W[(size_t)(nn0+mm)*K + k0+kk];
        }
        __syncthreads();
        #pragma unroll
        for(int kk=0;kk<16;kk++){
            float4 t0 = *(const float4*)&As[kk][ty*8];
            float4 t1 = *(const float4*)&As[kk][ty*8+4];
            ulonglong2 b0 = *(const ulonglong2*)&Bs[kk][tx*8];
            ulonglong2 b1 = *(const ulonglong2*)&Bs[kk][tx*8+4];
            U64 ad[8];
            ad[0]=pk2(t0.x,t0.x); ad[1]=pk2(t0.y,t0.y); ad[2]=pk2(t0.z,t0.z); ad[3]=pk2(t0.w,t0.w);
            ad[4]=pk2(t1.x,t1.x); ad[5]=pk2(t1.y,t1.y); ad[6]=pk2(t1.z,t1.z); ad[7]=pk2(t1.w,t1.w);
            #pragma unroll
            for(int i=0;i<8;i++){
                fma2(c[i][0],ad[i],b0.x); fma2(c[i][1],ad[i],b0.y);
                fma2(c[i][2],ad[i],b1.x); fma2(c[i][3],ad[i],b1.y);
            }
        }
        __syncthreads();
    }
    float* dst = (which==0)?g_q : (which==1)?g_k : g_v;
    #pragma unroll
    for(int i=0;i<8;i++){
        int m = m0 + ty*8 + i;
        #pragma unroll
        for(int jp=0;jp<4;jp++){
            float2 v = up2(c[i][jp]);
            #pragma unroll
            for(int l=0;l<2;l++){
                int nn = nn0 + tx*8 + jp*2 + l;
                float val = (l?v.y:v.x) + Bv[nn];
                if(which < 3){
                    int hh = nn>>5, dd2 = nn&31;
                    int bb = m>>10, ll = m&1023;
                    dst[(((size_t)(bb*HH+hh))*LL + ll)*DD + dd2] = val;
                } else {
                    g_g[(size_t)m*CA + nn] = val;
                }
            }
        }
    }
}

// -------------------- kernel 4: pair bias v7 --------------------
// 1 z-row per thread, ALL 16 heads (z read exactly once). f32x2 packed over
// adjacent z-channels; weights pre-packed (w_c, w_{c+1}) in smem (broadcast LDS).
__global__ __launch_bounds__(256) void bias_kernel(
    const float* __restrict__ z, const float* __restrict__ z_scale,
    const float* __restrict__ wz)
{
    __shared__ __align__(16) U64 wzs2[HH][CZ/2];   // (w_c, w_{c+1}) packed, 4KB
    __shared__ float wsum[HH];
    int tid = threadIdx.x;
    for(int e=tid;e<HH*(CZ/2);e+=256){
        int h = e>>5, c2 = e&31;
        float w0 = wz[h*CZ + 2*c2    ]*z_scale[2*c2    ];
        float w1 = wz[h*CZ + 2*c2 + 1]*z_scale[2*c2 + 1];
        wzs2[h][c2] = pk2(w0,w1);
    }
    __syncthreads();
    if(tid < HH){
        float S=0.f;
        for(int c2=0;c2<CZ/2;c2++){ float2 t=up2(wzs2[tid][c2]); S += t.x + t.y; }
        wsum[tid]=S;
    }
    __syncthreads();

    size_t t0 = (size_t)blockIdx.x*256 + tid;     // row index 0..2^21-1
    const float4* zp = (const float4*)(z + t0*CZ);

    U64 acc[HH];
    #pragma unroll
    for(int h=0;h<HH;h++) acc[h]=0ull;
    U64 sum=0ull, ssq=0ull;
    const U64 one2 = pk2(1.f,1.f);

    #pragma unroll
    for(int cs=0;cs<16;cs++){
        float4 a = zp[cs];
        U64 p01 = pk2(a.x,a.y);
        U64 p23 = pk2(a.z,a.w);
        fma2(sum,p01,one2); fma2(sum,p23,one2);
        fma2(ssq,p01,p01);  fma2(ssq,p23,p23);
        #pragma unroll
        for(int h=0;h<HH;h++){
            ulonglong2 w = *(const ulonglong2*)&wzs2[h][cs*2];
            fma2(acc[h],p01,w.x);
            fma2(acc[h],p23,w.y);
        }
    }
    float2 s2=up2(sum), q2=up2(ssq);
    float mean = (s2.x+s2.y)*(1.f/CZ);
    float var  = (q2.x+q2.y)*(1.f/CZ) - mean*mean;
    float rstd = rsqrtf(var + 1e-5f);

    int b_ = (int)(t0>>20), q_ = (int)((t0>>10)&1023), k_ = (int)(t0&1023);
    size_t ob = (((size_t)(b_*HH))*LL + q_)*LL + k_;
    #pragma unroll
    for(int h=0;h<HH;h++){
        float2 d = up2(acc[h]);
        float v = rstd*((d.x+d.y) - mean*wsum[h]);
        g_biash[ob + (size_t)h*LL*LL] = __float2half(v);
    }
}

// -------------------- kernel 5: attention (round-3 version) --------------------
__global__ __launch_bounds__(128) void attn_kernel(const int* __restrict__ mask)
{
    __shared__ __align__(16) float Ks[64*32];
    __shared__ __align__(16) float Vs[64*32];
    __shared__ __align__(16) __half bsh[64][80];
    __shared__ float mk[64];

    int tid = threadIdx.x;          // 128
    int b = blockIdx.z, h = blockIdx.y;
    int q0 = blockIdx.x*64;
    int row = tid >> 1;             // 0..63
    int half = tid & 1;             // which 16-d half

    const float* qp = g_q + (((size_t)(b*HH+h))*LL + q0+row)*DD + half*16;
    U64 qr2[8];
    #pragma unroll
    for(int i=0;i<4;i++){
        float4 t4 = ((const float4*)qp)[i];
        qr2[i*2]   = pk2(t4.x*SCALE, t4.y*SCALE);
        qr2[i*2+1] = pk2(t4.z*SCALE, t4.w*SCALE);
    }
    U64 O2[8];
    #pragma unroll
    for(int i=0;i<8;i++) O2[i]=0ull;
    float lrun = 0.f;

    const float* Kbase = g_k + ((size_t)(b*HH+h))*LL*DD;
    const float* Vbase = g_v + ((size_t)(b*HH+h))*LL*DD;
    const __half* bbase = g_biash + (((size_t)(b*HH+h))*LL + q0)*LL;

    for(int kt=0; kt<LL; kt+=64){
        __syncthreads();
        #pragma unroll
        for(int p=0;p<4;p++){
            int f = p*128 + tid;  // 512 float4s
            ((float4*)Ks)[f] = ((const float4*)(Kbase + (size_t)kt*DD))[f];
            ((float4*)Vs)[f] = ((const float4*)(Vbase + (size_t)kt*DD))[f];
        }
        #pragma unroll
        for(int p=0;p<4;p++){
            int c = p*128 + tid;   // 512 chunks of 8 halves
            int r = c>>3, part = c&7;
            *(float4*)&bsh[r][part*8] = ((const float4*)(bbase + (size_t)r*LL + kt))[part];
        }
        if(tid < 64) mk[tid] = mask[b*LL + kt + tid] ? 0.f : -10000.f;
        __syncthreads();

        #pragma unroll 2
        for(int j0=0;j0<64;j0+=4){
            const __half2* bp = (const __half2*)&bsh[row][j0];
            float2 b01 = __half22float2(bp[0]);
            float2 b23 = __half22float2(bp[1]);
            float bb4[4] = {b01.x, b01.y, b23.x, b23.y};
            #pragma unroll
            for(int jj=0;jj<4;jj++){
                int j = j0 + jj;
                const ulonglong2* kp = (const ulonglong2*)&Ks[j*32 + half*16];
                U64 sacc = 0ull;
                #pragma unroll
                for(int i=0;i<4;i++){
                    ulonglong2 kv = kp[i];
                    fma2(sacc, qr2[i*2],   kv.x);
                    fma2(sacc, qr2[i*2+1], kv.y);
                }
                float2 sp = up2(sacc);
                float part = sp.x + sp.y;
                float tot = part + __shfl_xor_sync(0xffffffffu, part, 1);
                float s_ = tot + bb4[jj] + mk[j];
                float p_ = __expf(s_);
                lrun += p_;
                U64 pp = pk2(p_, p_);
                const ulonglong2* vp = (const ulonglong2*)&Vs[j*32 + half*16];
                #pragma unroll
                for(int i=0;i<4;i++){
                    ulonglong2 vv = vp[i];
                    fma2(O2[i*2],   pp, vv.x);
                    fma2(O2[i*2+1], pp, vv.y);
                }
            }
        }
    }
    float inv = 1.f/fmaxf(lrun, 1e-20f);
    float* dst = g_ao + ((size_t)(b*LL + q0+row))*CA + h*DD + half*16;
    #pragma unroll
    for(int i=0;i<4;i++){
        float2 v0 = up2(O2[i*2]), v1 = up2(O2[i*2+1]);
        ((float4*)dst)[i] = make_float4(v0.x*inv, v0.y*inv, v1.x*inv, v1.y*inv);
    }
}

// -------------------- kernel 6: output GEMM (f32x2) --------------------
__global__ __launch_bounds__(256) void out_kernel(
    const float* __restrict__ wo, const float* __restrict__ bo,
    const int* __restrict__ mask, float* __restrict__ out)
{
    const int K = CA;
    __shared__ __align__(16) float As[16][72];
    __shared__ __align__(16) float Bs[16][72];
    int tid = threadIdx.x;
    int tx = tid & 15, ty = tid >> 4;
    int m0 = blockIdx.y*64, n0 = blockIdx.x*64;
    U64 c[4][2]={};
    for(int k0=0;k0<K;k0+=16){
        #pragma unroll
        for(int p=0;p<4;p++){
            int e = p*256 + tid;
            int mm = e>>4, kk = e&15;
            size_t ai = (size_t)(m0+mm)*K + k0+kk;
            As[kk][mm] = sigm(g_g[ai]) * g_ao[ai];
            Bs[kk][mm] = wo[(size_t)(n0+mm)*K + k0+kk];
        }
        __syncthreads();
        #pragma unroll
        for(int kk=0;kk<16;kk++){
            float4 a4 = *(const float4*)&As[kk][ty*4];
            ulonglong2 bu = *(const ulonglong2*)&Bs[kk][tx*4];
            U64 ad[4];
            ad[0]=pk2(a4.x,a4.x); ad[1]=pk2(a4.y,a4.y); ad[2]=pk2(a4.z,a4.z); ad[3]=pk2(a4.w,a4.w);
            #pragma unroll
            for(int i=0;i<4;i++){
                fma2(c[i][0],ad[i],bu.x);
                fma2(c[i][1],ad[i],bu.y);
            }
        }
        __syncthreads();
    }
    #pragma unroll
    for(int i=0;i<4;i++){
        int m = m0 + ty*4 + i;
        float mq = mask[m] ? 1.f : 0.f;
        #pragma unroll
        for(int jp=0;jp<2;jp++){
            float2 v = up2(c[i][jp]);
            int n = n0 + tx*4 + jp*2;
            out[(size_t)m*CA + n]   = (v.x + bo[n])   * g_glast[(size_t)m*CA + n]   * mq;
            out[(size_t)m*CA + n+1] = (v.y + bo[n+1]) * g_glast[(size_t)m*CA + n+1] * mq;
        }
    }
}

// -------------------- launch --------------------
extern "C" void kernel_launch(void* const* d_in, const int* in_sizes, int n_in,
                              void* d_out, int out_size)
{
    const float* a          = (const float*)d_in[0];
    const float* s          = (const float*)d_in[1];
    const float* z          = (const float*)d_in[2];
    const float* ln_s_scale = (const float*)d_in[3];
    const float* ada_w_s    = (const float*)d_in[4];
    const float* ada_b_s    = (const float*)d_in[5];
    const float* ada_w_nb   = (const float*)d_in[6];
    const float* wq = (const float*)d_in[7];  const float* bq = (const float*)d_in[8];
    const float* wk = (const float*)d_in[9];  const float* bk = (const float*)d_in[10];
    const float* wv = (const float*)d_in[11]; const float* bv = (const float*)d_in[12];
    const float* wg = (const float*)d_in[13]; const float* bg = (const float*)d_in[14];
    const float* wo = (const float*)d_in[15]; const float* bo = (const float*)d_in[16];
    const float* ln_z_scale = (const float*)d_in[17];
    const float* wz         = (const float*)d_in[18];
    const float* w_last     = (const float*)d_in[19];
    const float* b_last     = (const float*)d_in[20];
    const int*   mask       = (const int*)d_in[21];
    float* out = (float*)d_out;

    ln_kernel<<<MM, 256>>>(a, s, ln_s_scale);
    anorm_kernel<<<dim3(CA/64, MM/64), 256>>>(s, ada_w_s, ada_b_s, ada_w_nb, w_last, b_last);
    qkvg_kernel<<<dim3(2048/128, MM/128), 256>>>(wq,bq, wk,bk, wv,bv, wg,bg);
    bias_kernel<<<(BB*LL*LL)/256, 256>>>(z, ln_z_scale, wz);
    attn_kernel<<<dim3(LL/64, HH, BB), 128>>>(mask);
    out_kernel<<<dim3(CA/64, MM/64), 256>>>(wo, bo, mask, out);
}

// round 8
// speedup vs baseline: 1.6249x; 1.3514x over previous
#include <cuda_runtime.h>
#include <cuda_bf16.h>
#include <cuda_fp16.h>

// Problem constants
#define BB 2
#define LL 1024
#define CA 512
#define CS 384
#define CZ 64
#define HH 16
#define DD 32
#define MM (BB*LL)          // 2048 rows
#define SCALE 0.17677669529663687f  // 1/sqrt(32)

typedef unsigned long long U64;
__device__ __forceinline__ U64 pk2(float lo, float hi){ U64 r; asm("mov.b64 %0, {%1,%2};":"=l"(r):"f"(lo),"f"(hi)); return r; }
__device__ __forceinline__ void fma2(U64 &d, U64 a, U64 b){ asm("fma.rn.f32x2 %0, %1, %2, %3;":"=l"(d):"l"(a),"l"(b),"l"(d)); }
__device__ __forceinline__ float2 up2(U64 v){ float2 r; asm("mov.b64 {%0,%1}, %2;":"=f"(r.x),"=f"(r.y):"l"(v)); return r; }

// -------------------- device scratch --------------------
__device__ __align__(16) float g_s_ln[MM*CS];
__device__ __align__(16) float g_a_ln[MM*CA];
__device__ __align__(16) float g_anorm[MM*CA];
__device__ __align__(16) float g_glast[MM*CA];
__device__ __align__(16) float g_q[MM*CA];   // [b][h][l][d]
__device__ __align__(16) float g_k[MM*CA];
__device__ __align__(16) float g_v[MM*CA];
__device__ __align__(16) float g_g[MM*CA];   // pre-sigmoid gate
__device__ __align__(16) float g_ao[MM*CA];  // attention out [b][l][h*32+d]
__device__ __align__(16) __half g_biash[(size_t)BB*HH*LL*LL]; // 67MB fp16 bias

__device__ __forceinline__ float sigm(float x){ return 1.f/(1.f+__expf(-x)); }

// -------------------- kernel 1: row layernorms --------------------
__global__ __launch_bounds__(256) void ln_kernel(
    const float* __restrict__ a, const float* __restrict__ s,
    const float* __restrict__ s_scale)
{
    int row = blockIdx.x;
    int tid = threadIdx.x;
    __shared__ float rs[16];
    const float* ar = a + (size_t)row*CA;
    float x0 = ar[tid], x1 = ar[tid+256];
    float sum = x0+x1, ss = x0*x0 + x1*x1;
    #pragma unroll
    for(int o=16;o;o>>=1){ sum += __shfl_xor_sync(0xffffffffu,sum,o); ss += __shfl_xor_sync(0xffffffffu,ss,o); }
    if((tid&31)==0){ rs[tid>>5]=sum; rs[8+(tid>>5)]=ss; }
    __syncthreads();
    if(tid==0){ float S=0,Q=0; for(int i=0;i<8;i++){S+=rs[i];Q+=rs[8+i];} rs[0]=S; rs[8]=Q; }
    __syncthreads();
    float mean = rs[0]*(1.f/CA);
    float var  = rs[8]*(1.f/CA) - mean*mean;
    float rstd = rsqrtf(var + 1e-5f);
    g_a_ln[(size_t)row*CA + tid]      = (x0-mean)*rstd;
    g_a_ln[(size_t)row*CA + tid+256]  = (x1-mean)*rstd;
    __syncthreads();
    const float* sr = s + (size_t)row*CS;
    float y0 = sr[tid];
    float y1 = (tid < CS-256) ? sr[tid+256] : 0.f;
    sum = y0+y1; ss = y0*y0 + y1*y1;
    #pragma unroll
    for(int o=16;o;o>>=1){ sum += __shfl_xor_sync(0xffffffffu,sum,o); ss += __shfl_xor_sync(0xffffffffu,ss,o); }
    if((tid&31)==0){ rs[tid>>5]=sum; rs[8+(tid>>5)]=ss; }
    __syncthreads();
    if(tid==0){ float S=0,Q=0; for(int i=0;i<8;i++){S+=rs[i];Q+=rs[8+i];} rs[0]=S; rs[8]=Q; }
    __syncthreads();
    mean = rs[0]*(1.f/CS);
    var  = rs[8]*(1.f/CS) - mean*mean;
    rstd = rsqrtf(var + 1e-5f);
    g_s_ln[(size_t)row*CS + tid] = (y0-mean)*rstd*s_scale[tid];
    if(tid < CS-256)
        g_s_ln[(size_t)row*CS + tid+256] = (y1-mean)*rstd*s_scale[tid+256];
}

// -------------------- kernel 2: a_norm + glast (triple GEMM, f32x2) --------------------
__global__ __launch_bounds__(256) void anorm_kernel(
    const float* __restrict__ s_raw,
    const float* __restrict__ ada_w_s, const float* __restrict__ ada_b_s,
    const float* __restrict__ ada_w_nb,
    const float* __restrict__ w_last, const float* __restrict__ b_last)
{
    const int K = CS;
    __shared__ __align__(16) float As1[16][72];
    __shared__ __align__(16) float As2[16][72];
    __shared__ __align__(16) float Bs1[16][72];
    __shared__ __align__(16) float Bs2[16][72];
    __shared__ __align__(16) float Bs3[16][72];
    int tid = threadIdx.x;
    int tx = tid & 15, ty = tid >> 4;
    int m0 = blockIdx.y*64, n0 = blockIdx.x*64;
    U64 c1[4][2]={}, c2[4][2]={}, c3[4][2]={};
    for(int k0=0;k0<K;k0+=16){
        #pragma unroll
        for(int p=0;p<4;p++){
            int e = p*256 + tid;
            int mm = e>>4, kk = e&15;
            As1[kk][mm] = g_s_ln[(size_t)(m0+mm)*K + k0+kk];
            As2[kk][mm] = s_raw[(size_t)(m0+mm)*K + k0+kk];
            Bs1[kk][mm] = ada_w_s [(size_t)(n0+mm)*K + k0+kk];
            Bs2[kk][mm] = ada_w_nb[(size_t)(n0+mm)*K + k0+kk];
            Bs3[kk][mm] = w_last  [(size_t)(n0+mm)*K + k0+kk];
        }
        __syncthreads();
        #pragma unroll
        for(int kk=0;kk<16;kk++){
            float4 a1 = *(const float4*)&As1[kk][ty*4];
            float4 a2 = *(const float4*)&As2[kk][ty*4];
            ulonglong2 b1 = *(const ulonglong2*)&Bs1[kk][tx*4];
            ulonglong2 b2 = *(const ulonglong2*)&Bs2[kk][tx*4];
            ulonglong2 b3 = *(const ulonglong2*)&Bs3[kk][tx*4];
            U64 a1d[4], a2d[4];
            a1d[0]=pk2(a1.x,a1.x); a1d[1]=pk2(a1.y,a1.y); a1d[2]=pk2(a1.z,a1.z); a1d[3]=pk2(a1.w,a1.w);
            a2d[0]=pk2(a2.x,a2.x); a2d[1]=pk2(a2.y,a2.y); a2d[2]=pk2(a2.z,a2.z); a2d[3]=pk2(a2.w,a2.w);
            #pragma unroll
            for(int i=0;i<4;i++){
                fma2(c1[i][0],a1d[i],b1.x); fma2(c1[i][1],a1d[i],b1.y);
                fma2(c2[i][0],a1d[i],b2.x); fma2(c2[i][1],a1d[i],b2.y);
                fma2(c3[i][0],a2d[i],b3.x); fma2(c3[i][1],a2d[i],b3.y);
            }
        }
        __syncthreads();
    }
    #pragma unroll
    for(int i=0;i<4;i++){
        int m = m0 + ty*4 + i;
        #pragma unroll
        for(int jp=0;jp<2;jp++){
            float2 v1 = up2(c1[i][jp]), v2 = up2(c2[i][jp]), v3 = up2(c3[i][jp]);
            int n = n0 + tx*4 + jp*2;
            float sgA = sigm(v1.x + ada_b_s[n]);
            float sgB = sigm(v1.y + ada_b_s[n+1]);
            g_anorm[(size_t)m*CA + n]   = sgA * g_a_ln[(size_t)m*CA + n]   + v2.x;
            g_anorm[(size_t)m*CA + n+1] = sgB * g_a_ln[(size_t)m*CA + n+1] + v2.y;
            g_glast[(size_t)m*CA + n]   = sigm(v3.x + b_last[n]);
            g_glast[(size_t)m*CA + n+1] = sigm(v3.y + b_last[n+1]);
        }
    }
}

// -------------------- kernel 3: QKVG projections (f32x2) --------------------
__global__ __launch_bounds__(256) void qkvg_kernel(
    const float* __restrict__ wq, const float* __restrict__ bq,
    const float* __restrict__ wk, const float* __restrict__ bk,
    const float* __restrict__ wv, const float* __restrict__ bv,
    const float* __restrict__ wg, const float* __restrict__ bg)
{
    const int K = CA;
    __shared__ __align__(16) float As[16][136];
    __shared__ __align__(16) float Bs[16][136];
    int tid = threadIdx.x;
    int tx = tid & 15, ty = tid >> 4;
    int m0 = blockIdx.y*128;
    int n0 = blockIdx.x*128;
    int which = n0 >> 9;
    int nn0 = n0 & 511;
    const float* W  = (which==0)?wq : (which==1)?wk : (which==2)?wv : wg;
    const float* Bv = (which==0)?bq : (which==1)?bk : (which==2)?bv : bg;
    U64 c[8][4]={};
    for(int k0=0;k0<K;k0+=16){
        #pragma unroll
        for(int p=0;p<8;p++){
            int e = p*256 + tid;
            int mm = e>>4, kk = e&15;
            As[kk][mm] = g_anorm[(size_t)(m0+mm)*K + k0+kk];
            Bs[kk][mm] = W[(size_t)(nn0+mm)*K + k0+kk];
        }
        __syncthreads();
        #pragma unroll
        for(int kk=0;kk<16;kk++){
            float4 t0 = *(const float4*)&As[kk][ty*8];
            float4 t1 = *(const float4*)&As[kk][ty*8+4];
            ulonglong2 b0 = *(const ulonglong2*)&Bs[kk][tx*8];
            ulonglong2 b1 = *(const ulonglong2*)&Bs[kk][tx*8+4];
            U64 ad[8];
            ad[0]=pk2(t0.x,t0.x); ad[1]=pk2(t0.y,t0.y); ad[2]=pk2(t0.z,t0.z); ad[3]=pk2(t0.w,t0.w);
            ad[4]=pk2(t1.x,t1.x); ad[5]=pk2(t1.y,t1.y); ad[6]=pk2(t1.z,t1.z); ad[7]=pk2(t1.w,t1.w);
            #pragma unroll
            for(int i=0;i<8;i++){
                fma2(c[i][0],ad[i],b0.x); fma2(c[i][1],ad[i],b0.y);
                fma2(c[i][2],ad[i],b1.x); fma2(c[i][3],ad[i],b1.y);
            }
        }
        __syncthreads();
    }
    float* dst = (which==0)?g_q : (which==1)?g_k : g_v;
    #pragma unroll
    for(int i=0;i<8;i++){
        int m = m0 + ty*8 + i;
        #pragma unroll
        for(int jp=0;jp<4;jp++){
            float2 v = up2(c[i][jp]);
            #pragma unroll
            for(int l=0;l<2;l++){
                int nn = nn0 + tx*8 + jp*2 + l;
                float val = (l?v.y:v.x) + Bv[nn];
                if(which < 3){
                    int hh = nn>>5, dd2 = nn&31;
                    int bb = m>>10, ll = m&1023;
                    dst[(((size_t)(bb*HH+hh))*LL + ll)*DD + dd2] = val;
                } else {
                    g_g[(size_t)m*CA + nn] = val;
                }
            }
        }
    }
}

// -------------------- kernel 4: pair bias v8 (mask-skip) --------------------
// bias[b,h,q,k] only matters when mask[b,q]&&mask[b,k]; otherwise store 0 and
// skip the z read + LN + 16 dots (~75% of rows skipped).
__global__ __launch_bounds__(256) void bias_kernel(
    const float* __restrict__ z, const float* __restrict__ z_scale,
    const float* __restrict__ wz, const int* __restrict__ mask)
{
    __shared__ __align__(16) U64 wzs2[HH][CZ/2];   // (w_c, w_{c+1}) packed, 4KB
    __shared__ float wsum[HH];
    int tid = threadIdx.x;
    for(int e=tid;e<HH*(CZ/2);e+=256){
        int h = e>>5, c2 = e&31;
        float w0 = wz[h*CZ + 2*c2    ]*z_scale[2*c2    ];
        float w1 = wz[h*CZ + 2*c2 + 1]*z_scale[2*c2 + 1];
        wzs2[h][c2] = pk2(w0,w1);
    }
    __syncthreads();
    if(tid < HH){
        float S=0.f;
        for(int c2=0;c2<CZ/2;c2++){ float2 t=up2(wzs2[tid][c2]); S += t.x + t.y; }
        wsum[tid]=S;
    }
    __syncthreads();

    size_t t0 = (size_t)blockIdx.x*256 + tid;     // row index 0..2^21-1
    int b_ = (int)(t0>>20), q_ = (int)((t0>>10)&1023), k_ = (int)(t0&1023);
    size_t ob = (((size_t)(b_*HH))*LL + q_)*LL + k_;

    bool active = (mask[b_*LL + q_] != 0) && (mask[b_*LL + k_] != 0);
    if(!active){
        __half zh = __float2half(0.f);
        #pragma unroll
        for(int h=0;h<HH;h++) g_biash[ob + (size_t)h*LL*LL] = zh;
        return;
    }

    const float4* zp = (const float4*)(z + t0*CZ);
    U64 acc[HH];
    #pragma unroll
    for(int h=0;h<HH;h++) acc[h]=0ull;
    U64 sum=0ull, ssq=0ull;
    const U64 one2 = pk2(1.f,1.f);

    #pragma unroll
    for(int cs=0;cs<16;cs++){
        float4 a = zp[cs];
        U64 p01 = pk2(a.x,a.y);
        U64 p23 = pk2(a.z,a.w);
        fma2(sum,p01,one2); fma2(sum,p23,one2);
        fma2(ssq,p01,p01);  fma2(ssq,p23,p23);
        #pragma unroll
        for(int h=0;h<HH;h++){
            ulonglong2 w = *(const ulonglong2*)&wzs2[h][cs*2];
            fma2(acc[h],p01,w.x);
            fma2(acc[h],p23,w.y);
        }
    }
    float2 s2=up2(sum), q2=up2(ssq);
    float mean = (s2.x+s2.y)*(1.f/CZ);
    float var  = (q2.x+q2.y)*(1.f/CZ) - mean*mean;
    float rstd = rsqrtf(var + 1e-5f);

    #pragma unroll
    for(int h=0;h<HH;h++){
        float2 d = up2(acc[h]);
        float v = rstd*((d.x+d.y) - mean*wsum[h]);
        g_biash[ob + (size_t)h*LL*LL] = __float2half(v);
    }
}

// -------------------- kernel 5: attention (uniform mask-skip on j) --------------
__global__ __launch_bounds__(128) void attn_kernel(const int* __restrict__ mask)
{
    __shared__ __align__(16) float Ks[64*32];
    __shared__ __align__(16) float Vs[64*32];
    __shared__ __align__(16) __half bsh[64][80];
    __shared__ float mk[64];

    int tid = threadIdx.x;          // 128
    int b = blockIdx.z, h = blockIdx.y;
    int q0 = blockIdx.x*64;
    int row = tid >> 1;             // 0..63
    int half = tid & 1;             // which 16-d half

    const float* qp = g_q + (((size_t)(b*HH+h))*LL + q0+row)*DD + half*16;
    U64 qr2[8];
    #pragma unroll
    for(int i=0;i<4;i++){
        float4 t4 = ((const float4*)qp)[i];
        qr2[i*2]   = pk2(t4.x*SCALE, t4.y*SCALE);
        qr2[i*2+1] = pk2(t4.z*SCALE, t4.w*SCALE);
    }
    U64 O2[8];
    #pragma unroll
    for(int i=0;i<8;i++) O2[i]=0ull;
    float lrun = 0.f;

    const float* Kbase = g_k + ((size_t)(b*HH+h))*LL*DD;
    const float* Vbase = g_v + ((size_t)(b*HH+h))*LL*DD;
    const __half* bbase = g_biash + (((size_t)(b*HH+h))*LL + q0)*LL;

    for(int kt=0; kt<LL; kt+=64){
        __syncthreads();
        #pragma unroll
        for(int p=0;p<4;p++){
            int f = p*128 + tid;  // 512 float4s
            ((float4*)Ks)[f] = ((const float4*)(Kbase + (size_t)kt*DD))[f];
            ((float4*)Vs)[f] = ((const float4*)(Vbase + (size_t)kt*DD))[f];
        }
        #pragma unroll
        for(int p=0;p<4;p++){
            int c = p*128 + tid;   // 512 chunks of 8 halves
            int r = c>>3, part = c&7;
            *(float4*)&bsh[r][part*8] = ((const float4*)(bbase + (size_t)r*LL + kt))[part];
        }
        if(tid < 64) mk[tid] = mask[b*LL + kt + tid] ? 0.f : -10000.f;
        __syncthreads();

        for(int j0=0;j0<64;j0+=4){
            const __half2* bp = (const __half2*)&bsh[row][j0];
            float2 b01 = __half22float2(bp[0]);
            float2 b23 = __half22float2(bp[1]);
            float bb4[4] = {b01.x, b01.y, b23.x, b23.y};
            #pragma unroll
            for(int jj=0;jj<4;jj++){
                int j = j0 + jj;
                if(mk[j] == 0.f){   // uniform across block: skip masked keys (exp==0)
                    const ulonglong2* kp = (const ulonglong2*)&Ks[j*32 + half*16];
                    U64 sacc = 0ull;
                    #pragma unroll
                    for(int i=0;i<4;i++){
                        ulonglong2 kv = kp[i];
                        fma2(sacc, qr2[i*2],   kv.x);
                        fma2(sacc, qr2[i*2+1], kv.y);
                    }
                    float2 sp = up2(sacc);
                    float part = sp.x + sp.y;
                    float tot = part + __shfl_xor_sync(0xffffffffu, part, 1);
                    float s_ = tot + bb4[jj];
                    float p_ = __expf(s_);
                    lrun += p_;
                    U64 pp = pk2(p_, p_);
                    const ulonglong2* vp = (const ulonglong2*)&Vs[j*32 + half*16];
                    #pragma unroll
                    for(int i=0;i<4;i++){
                        ulonglong2 vv = vp[i];
                        fma2(O2[i*2],   pp, vv.x);
                        fma2(O2[i*2+1], pp, vv.y);
                    }
                }
            }
        }
    }
    float inv = 1.f/fmaxf(lrun, 1e-20f);
    float* dst = g_ao + ((size_t)(b*LL + q0+row))*CA + h*DD + half*16;
    #pragma unroll
    for(int i=0;i<4;i++){
        float2 v0 = up2(O2[i*2]), v1 = up2(O2[i*2+1]);
        ((float4*)dst)[i] = make_float4(v0.x*inv, v0.y*inv, v1.x*inv, v1.y*inv);
    }
}

// -------------------- kernel 6: output GEMM (f32x2) --------------------
__global__ __launch_bounds__(256) void out_kernel(
    const float* __restrict__ wo, const float* __restrict__ bo,
    const int* __restrict__ mask, float* __restrict__ out)
{
    const int K = CA;
    __shared__ __align__(16) float As[16][72];
    __shared__ __align__(16) float Bs[16][72];
    int tid = threadIdx.x;
    int tx = tid & 15, ty = tid >> 4;
    int m0 = blockIdx.y*64, n0 = blockIdx.x*64;
    U64 c[4][2]={};
    for(int k0=0;k0<K;k0+=16){
        #pragma unroll
        for(int p=0;p<4;p++){
            int e = p*256 + tid;
            int mm = e>>4, kk = e&15;
            size_t ai = (size_t)(m0+mm)*K + k0+kk;
            As[kk][mm] = sigm(g_g[ai]) * g_ao[ai];
            Bs[kk][mm] = wo[(size_t)(n0+mm)*K + k0+kk];
        }
        __syncthreads();
        #pragma unroll
        for(int kk=0;kk<16;kk++){
            float4 a4 = *(const float4*)&As[kk][ty*4];
            ulonglong2 bu = *(const ulonglong2*)&Bs[kk][tx*4];
            U64 ad[4];
            ad[0]=pk2(a4.x,a4.x); ad[1]=pk2(a4.y,a4.y); ad[2]=pk2(a4.z,a4.z); ad[3]=pk2(a4.w,a4.w);
            #pragma unroll
            for(int i=0;i<4;i++){
                fma2(c[i][0],ad[i],bu.x);
                fma2(c[i][1],ad[i],bu.y);
            }
        }
        __syncthreads();
    }
    #pragma unroll
    for(int i=0;i<4;i++){
        int m = m0 + ty*4 + i;
        float mq = mask[m] ? 1.f : 0.f;
        #pragma unroll
        for(int jp=0;jp<2;jp++){
            float2 v = up2(c[i][jp]);
            int n = n0 + tx*4 + jp*2;
            out[(size_t)m*CA + n]   = (v.x + bo[n])   * g_glast[(size_t)m*CA + n]   * mq;
            out[(size_t)m*CA + n+1] = (v.y + bo[n+1]) * g_glast[(size_t)m*CA + n+1] * mq;
        }
    }
}

// -------------------- launch --------------------
extern "C" void kernel_launch(void* const* d_in, const int* in_sizes, int n_in,
                              void* d_out, int out_size)
{
    const float* a          = (const float*)d_in[0];
    const float* s          = (const float*)d_in[1];
    const float* z          = (const float*)d_in[2];
    const float* ln_s_scale = (const float*)d_in[3];
    const float* ada_w_s    = (const float*)d_in[4];
    const float* ada_b_s    = (const float*)d_in[5];
    const float* ada_w_nb   = (const float*)d_in[6];
    const float* wq = (const float*)d_in[7];  const float* bq = (const float*)d_in[8];
    const float* wk = (const float*)d_in[9];  const float* bk = (const float*)d_in[10];
    const float* wv = (const float*)d_in[11]; const float* bv = (const float*)d_in[12];
    const float* wg = (const float*)d_in[13]; const float* bg = (const float*)d_in[14];
    const float* wo = (const float*)d_in[15]; const float* bo = (const float*)d_in[16];
    const float* ln_z_scale = (const float*)d_in[17];
    const float* wz         = (const float*)d_in[18];
    const float* w_last     = (const float*)d_in[19];
    const float* b_last     = (const float*)d_in[20];
    const int*   mask       = (const int*)d_in[21];
    float* out = (float*)d_out;

    ln_kernel<<<MM, 256>>>(a, s, ln_s_scale);
    anorm_kernel<<<dim3(CA/64, MM/64), 256>>>(s, ada_w_s, ada_b_s, ada_w_nb, w_last, b_last);
    qkvg_kernel<<<dim3(2048/128, MM/128), 256>>>(wq,bq, wk,bk, wv,bv, wg,bg);
    bias_kernel<<<(BB*LL*LL)/256, 256>>>(z, ln_z_scale, wz, mask);
    attn_kernel<<<dim3(LL/64, HH, BB), 128>>>(mask);
    out_kernel<<<dim3(CA/64, MM/64), 256>>>(wo, bo, mask, out);
}